// round 14
// baseline (speedup 1.0000x reference)
#include <cuda_runtime.h>
#include <math.h>
#include <stdint.h>

#define NTOK 2048
#define DIM  512
#define NEXP 16
#define TOPK 2
#define HIDD 2048
#define NASSIGN (NTOK*TOPK)

// ---------------- scratch (device globals: no allocation allowed) ----------
__device__ float g_xn[NTOK*DIM];          // 4 MB  normalized activations
__device__ float g_H [NASSIGN*HIDD];      // 32 MB silu(h) per assignment row
__device__ float g_Y [NASSIGN*DIM];       // 8 MB  expert outputs per assignment row
__device__ int   g_cnt[NEXP];
__device__ int   g_off[NEXP+1];
__device__ int   g_tok[NEXP*NTOK];        // per-expert token lists
__device__ float g_gate[NTOK*TOPK];
__device__ int   g_se[NTOK*TOPK];         // expert id per (token,k)
__device__ int   g_sp[NTOK*TOPK];         // position within expert list per (token,k)

// ---- helpers --------------------------------------------------------------
__device__ __forceinline__ void mma_tf32(float* c, const uint32_t* a, const uint32_t* b) {
    asm("mma.sync.aligned.m16n8k8.row.col.f32.tf32.tf32.f32 "
        "{%0,%1,%2,%3}, {%4,%5,%6,%7}, {%8,%9}, {%0,%1,%2,%3};"
        : "+f"(c[0]), "+f"(c[1]), "+f"(c[2]), "+f"(c[3])
        : "r"(a[0]), "r"(a[1]), "r"(a[2]), "r"(a[3]), "r"(b[0]), "r"(b[1]));
}
__device__ __forceinline__ void cp16(uint32_t dst_smem, const void* src, bool valid) {
    const int sz = valid ? 16 : 0;
    asm volatile("cp.async.cg.shared.global [%0], [%1], 16, %2;"
                 :: "r"(dst_smem), "l"(src), "r"(sz));
}
__device__ __forceinline__ void cp4(uint32_t dst_smem, const void* src) {
    asm volatile("cp.async.ca.shared.global [%0], [%1], 4;"
                 :: "r"(dst_smem), "l"(src));
}
__device__ __forceinline__ uint32_t smem_u32(const void* p) {
    return (uint32_t)__cvta_generic_to_shared(p);
}

// ---------------------------------------------------------------------------
__global__ void zero_cnt_kernel() {
    if (threadIdx.x < NEXP) g_cnt[threadIdx.x] = 0;
}

// warp-per-token router: 16 tokens per 512-thread block, Wr staged once/block
__global__ __launch_bounds__(512)
void router_kernel(const float* __restrict__ x, const float* __restrict__ wn,
                   const float* __restrict__ Wr, const float* __restrict__ br) {
    __shared__ float WrT[16][520];   // transposed [e][d], padded: ~33 KB

    const int tid = threadIdx.x, lane = tid & 31, w = tid >> 5;

    // stage Wr transposed: thread d scatters its 16 expert weights
    {
        const float4* wg = (const float4*)(Wr + tid * 16);
        float4 r0 = wg[0], r1 = wg[1], r2 = wg[2], r3 = wg[3];
        float v[16] = { r0.x,r0.y,r0.z,r0.w, r1.x,r1.y,r1.z,r1.w,
                        r2.x,r2.y,r2.z,r2.w, r3.x,r3.y,r3.z,r3.w };
        #pragma unroll
        for (int e = 0; e < 16; e++) WrT[e][tid] = v[e];
    }
    __syncthreads();

    const int n = blockIdx.x * 16 + w;

    float xl[16];
    #pragma unroll
    for (int i = 0; i < 16; i++) xl[i] = x[n*DIM + i*32 + lane];

    float ss = 0.f;
    #pragma unroll
    for (int i = 0; i < 16; i++) ss += xl[i] * xl[i];
    #pragma unroll
    for (int o = 16; o > 0; o >>= 1) ss += __shfl_down_sync(0xffffffffu, ss, o);
    ss = __shfl_sync(0xffffffffu, ss, 0);
    const float rinv = rsqrtf(ss / (float)DIM + 1e-10f);

    float xnl[16];
    #pragma unroll
    for (int i = 0; i < 16; i++) {
        xnl[i] = wn[i*32 + lane] * xl[i] * rinv;
        g_xn[n*DIM + i*32 + lane] = xnl[i];
    }

    float le[16];
    #pragma unroll
    for (int e = 0; e < 16; e++) {
        float p = 0.f;
        #pragma unroll
        for (int i = 0; i < 16; i++) p += xnl[i] * WrT[e][i*32 + lane];
        #pragma unroll
        for (int o = 16; o > 0; o >>= 1) p += __shfl_down_sync(0xffffffffu, p, o);
        le[e] = p;                       // complete on lane 0
    }

    if (lane == 0) {
        #pragma unroll
        for (int e = 0; e < 16; e++) le[e] += br[e];
        int i0 = 0; float b0 = le[0];
        #pragma unroll
        for (int e = 1; e < 16; e++) if (le[e] > b0) { b0 = le[e]; i0 = e; }
        int i1 = -1; float b1 = -1e30f;
        #pragma unroll
        for (int e = 0; e < 16; e++) {
            if (e == i0) continue;
            if (le[e] > b1) { b1 = le[e]; i1 = e; }
        }
        const float z  = expf(b1 - b0);
        const float w0 = 1.f / (1.f + z);
        const float w1 = z   / (1.f + z);
        const int p0 = atomicAdd(&g_cnt[i0], 1);
        const int p1 = atomicAdd(&g_cnt[i1], 1);
        g_tok[i0*NTOK + p0] = n;
        g_tok[i1*NTOK + p1] = n;
        g_gate[n*2+0] = w0;  g_gate[n*2+1] = w1;
        g_se[n*2+0]   = i0;  g_se[n*2+1]   = i1;
        g_sp[n*2+0]   = p0;  g_sp[n*2+1]   = p1;
    }
}

__global__ void offsets_kernel() {
    if (threadIdx.x == 0) {
        int s = 0;
        #pragma unroll
        for (int e = 0; e < NEXP; e++) { g_off[e] = s; s += g_cnt[e]; }
        g_off[NEXP] = s;
    }
}

// ---------------------------------------------------------------------------
// TF32 mma.sync GEMM, 3-stage cp.async pipeline, one barrier per k-tile.
// BM=128, BN=128, BK=16, 256 threads = 8 warps (4m x 2n), warp tile 32x64.
// B stored PERMUTED in smem: n -> (n%8)*16 + n/8, so a thread's 8 nt-fragments
// for fixed (t,g) are contiguous: col = g*16 + wn*8 + nt  => 2x LDS.128 per
// k-row instead of 8 scalar LDS. Bs stride 140 words => fragment loads are
// conflict-free per quarter-warp ((12t+16g) distinct mod 32).
// FIRST=1: H[off+m] = silu(gather(xn)@W1[e] + b1[e])   (K=512,  LDB=HIDD)
// FIRST=0: Y[off+m] =        H        @W2[e] + b2[e]   (K=2048, LDB=DIM)
template<int FIRST>
__global__ __launch_bounds__(256, 2)
void ffn_mma_kernel(const float* __restrict__ W, const float* __restrict__ bias) {
    const int e  = blockIdx.z;
    const int ne = g_cnt[e];
    const int m0 = blockIdx.x * 128;
    if (m0 >= ne) return;
    const int n0  = blockIdx.y * 128;
    const int off = g_off[e];
    const int tid  = threadIdx.x;
    const int lane = tid & 31, warp = tid >> 5;
    const int g = lane >> 2, t = lane & 3;
    const int wm = warp & 3, wn = warp >> 2;

    constexpr int K   = FIRST ? DIM  : HIDD;
    constexpr int LDB = FIRST ? HIDD : DIM;
    const float* Bp = W + (size_t)e * K * LDB + n0;

    // dynamic smem: 3 x As[128][20], then 3 x Bs[16][140]
    extern __shared__ __align__(16) float smem[];
    float (*As)[128][20] = (float (*)[128][20])smem;
    float (*Bs)[16][140] = (float (*)[16][140])(smem + 3*128*20);

    // A cp.async mapping: 2 float4/thread; idx = tid + p*256 -> row idx>>2, col (idx&3)*4
    const float* arp[2];
    int arow[2], acol[2];
    #pragma unroll
    for (int p = 0; p < 2; p++) {
        const int idx = tid + p*256;
        arow[p] = idx >> 2;
        acol[p] = (idx & 3) * 4;
        const int m = m0 + arow[p];
        const float* ap = nullptr;
        if (m < ne) {
            if (FIRST) ap = g_xn + (size_t)g_tok[e*NTOK + m] * DIM;
            else       ap = g_H  + (size_t)(off + m) * HIDD;
        }
        arp[p] = ap;
    }
    // B cp.async mapping (4B, permuted dst): r = tid>>4, a = tid&15, j=0..7:
    //   src n = a*8 + j   ->  dst col = j*16 + a
    const int br_ = tid >> 4;
    const int ba  = tid & 15;

    float acc[2][8][4];
    #pragma unroll
    for (int mt = 0; mt < 2; mt++)
        #pragma unroll
        for (int nt = 0; nt < 8; nt++)
            #pragma unroll
            for (int i = 0; i < 4; i++) acc[mt][nt][i] = 0.f;

    auto issue = [&](int s, int k0) {
        #pragma unroll
        for (int p = 0; p < 2; p++) {
            const bool v = (arp[p] != nullptr);
            const float* src = v ? (arp[p] + k0 + acol[p]) : g_xn;  // dummy src when sz=0
            cp16(smem_u32(&As[s][arow[p]][acol[p]]), src, v);
        }
        const float* bsrc = Bp + (size_t)(k0 + br_) * LDB + ba*8;
        #pragma unroll
        for (int j = 0; j < 8; j++)
            cp4(smem_u32(&Bs[s][br_][j*16 + ba]), bsrc + j);
        asm volatile("cp.async.commit_group;");
    };

    constexpr int NT = K / 16;
    issue(0, 0);
    issue(1, 16);

    int cur = 0;                      // it % 3
    for (int it = 0; it < NT; it++) {
        if (it < NT - 1) asm volatile("cp.async.wait_group 1;");
        else             asm volatile("cp.async.wait_group 0;");
        __syncthreads();

        if (it + 2 < NT) {
            int s2 = cur + 2; if (s2 >= 3) s2 -= 3;
            issue(s2, (it + 2) * 16);
        }

        const int bbase = g*16 + wn*8;
        #pragma unroll
        for (int kk0 = 0; kk0 < 16; kk0 += 8) {
            uint32_t a[2][4];
            #pragma unroll
            for (int mt = 0; mt < 2; mt++) {
                const int row = wm*32 + mt*16 + g;
                a[mt][0] = __float_as_uint(As[cur][row  ][kk0 + t]);
                a[mt][1] = __float_as_uint(As[cur][row+8][kk0 + t]);
                a[mt][2] = __float_as_uint(As[cur][row  ][kk0 + t + 4]);
                a[mt][3] = __float_as_uint(As[cur][row+8][kk0 + t + 4]);
            }
            // vectorized b-fragments: nt 0..3 and 4..7 contiguous
            float4 u0 = *(const float4*)&Bs[cur][kk0 + t    ][bbase];
            float4 u1 = *(const float4*)&Bs[cur][kk0 + t    ][bbase + 4];
            float4 u2 = *(const float4*)&Bs[cur][kk0 + t + 4][bbase];
            float4 u3 = *(const float4*)&Bs[cur][kk0 + t + 4][bbase + 4];
            uint32_t b[8][2];
            b[0][0]=__float_as_uint(u0.x); b[1][0]=__float_as_uint(u0.y);
            b[2][0]=__float_as_uint(u0.z); b[3][0]=__float_as_uint(u0.w);
            b[4][0]=__float_as_uint(u1.x); b[5][0]=__float_as_uint(u1.y);
            b[6][0]=__float_as_uint(u1.z); b[7][0]=__float_as_uint(u1.w);
            b[0][1]=__float_as_uint(u2.x); b[1][1]=__float_as_uint(u2.y);
            b[2][1]=__float_as_uint(u2.z); b[3][1]=__float_as_uint(u2.w);
            b[4][1]=__float_as_uint(u3.x); b[5][1]=__float_as_uint(u3.y);
            b[6][1]=__float_as_uint(u3.z); b[7][1]=__float_as_uint(u3.w);
            #pragma unroll
            for (int mt = 0; mt < 2; mt++)
                #pragma unroll
                for (int nt = 0; nt < 8; nt++)
                    mma_tf32(acc[mt][nt], a[mt], b[nt]);
        }

        if (++cur == 3) cur = 0;
    }

    // ---- epilogue: bias (+silu), write ----
    const float* bpr = bias + (size_t)e * LDB + n0;
    #pragma unroll
    for (int mt = 0; mt < 2; mt++) {
        #pragma unroll
        for (int r = 0; r < 2; r++) {
            const int m = m0 + wm*32 + mt*16 + g + r*8;
            if (m >= ne) continue;
            float* orow = (FIRST ? g_H + (size_t)(off + m) * HIDD
                                 : g_Y + (size_t)(off + m) * DIM) + n0;
            #pragma unroll
            for (int nt = 0; nt < 8; nt++) {
                const int lc = wn*64 + nt*8 + 2*t;
                float v0 = acc[mt][nt][r*2+0] + bpr[lc];
                float v1 = acc[mt][nt][r*2+1] + bpr[lc+1];
                if (FIRST) {
                    v0 = v0 / (1.f + expf(-v0));   // silu
                    v1 = v1 / (1.f + expf(-v1));
                }
                *(float2*)(orow + lc) = make_float2(v0, v1);
            }
        }
    }
}

// out = x + g0*Y[row0] + g1*Y[row1]   (fixed k order -> deterministic)
__global__ void combine_kernel(const float* __restrict__ x, float* __restrict__ out) {
    const int idx = blockIdx.x * blockDim.x + threadIdx.x;
    if (idx >= NTOK*DIM) return;
    const int n = idx / DIM, d = idx % DIM;
    const int r0 = g_off[g_se[n*2+0]] + g_sp[n*2+0];
    const int r1 = g_off[g_se[n*2+1]] + g_sp[n*2+1];
    out[idx] = x[idx]
             + g_gate[n*2+0] * g_Y[(size_t)r0*DIM + d]
             + g_gate[n*2+1] * g_Y[(size_t)r1*DIM + d];
}

// ---------------------------------------------------------------------------
extern "C" void kernel_launch(void* const* d_in, const int* in_sizes, int n_in,
                              void* d_out, int out_size) {
    const float* x  = (const float*)d_in[0];
    const float* wn = (const float*)d_in[1];
    const float* Wr = (const float*)d_in[2];
    const float* br = (const float*)d_in[3];
    const float* W1 = (const float*)d_in[4];
    const float* b1 = (const float*)d_in[5];
    const float* W2 = (const float*)d_in[6];
    const float* b2 = (const float*)d_in[7];
    float* out = (float*)d_out;

    const int SMEM = (3*128*20 + 3*16*140) * 4;   // 57600 B
    cudaFuncSetAttribute(ffn_mma_kernel<1>,
                         cudaFuncAttributeMaxDynamicSharedMemorySize, SMEM);
    cudaFuncSetAttribute(ffn_mma_kernel<0>,
                         cudaFuncAttributeMaxDynamicSharedMemorySize, SMEM);

    zero_cnt_kernel<<<1, 32>>>();
    router_kernel<<<NTOK/16, 512>>>(x, wn, Wr, br);
    offsets_kernel<<<1, 32>>>();
    ffn_mma_kernel<1><<<dim3(16, HIDD/128, NEXP), 256, SMEM>>>(W1, b1);
    ffn_mma_kernel<0><<<dim3(16, DIM /128, NEXP), 256, SMEM>>>(W2, b2);
    combine_kernel<<<(NTOK*DIM + 255)/256, 256>>>(x, out);
}

// round 15
// speedup vs baseline: 1.4254x; 1.4254x over previous
#include <cuda_runtime.h>
#include <math.h>
#include <stdint.h>

#define NTOK 2048
#define DIM  512
#define NEXP 16
#define TOPK 2
#define HIDD 2048
#define NASSIGN (NTOK*TOPK)

// ---------------- scratch (device globals: no allocation allowed) ----------
__device__ float g_xn[NTOK*DIM];          // 4 MB  normalized activations
__device__ float g_H [NASSIGN*HIDD];      // 32 MB silu(h) per assignment row
__device__ float g_Y [NASSIGN*DIM];       // 8 MB  expert outputs per assignment row
__device__ int   g_cnt[NEXP];
__device__ int   g_off[NEXP+1];
__device__ int   g_tok[NEXP*NTOK];        // per-expert token lists
__device__ float g_gate[NTOK*TOPK];
__device__ int   g_se[NTOK*TOPK];         // expert id per (token,k)
__device__ int   g_sp[NTOK*TOPK];         // position within expert list per (token,k)

// ---- helpers --------------------------------------------------------------
__device__ __forceinline__ void mma_tf32(float* c, const uint32_t* a, const uint32_t* b) {
    asm("mma.sync.aligned.m16n8k8.row.col.f32.tf32.tf32.f32 "
        "{%0,%1,%2,%3}, {%4,%5,%6,%7}, {%8,%9}, {%0,%1,%2,%3};"
        : "+f"(c[0]), "+f"(c[1]), "+f"(c[2]), "+f"(c[3])
        : "r"(a[0]), "r"(a[1]), "r"(a[2]), "r"(a[3]), "r"(b[0]), "r"(b[1]));
}
__device__ __forceinline__ void cp16(uint32_t dst_smem, const void* src, bool valid) {
    const int sz = valid ? 16 : 0;
    asm volatile("cp.async.cg.shared.global [%0], [%1], 16, %2;"
                 :: "r"(dst_smem), "l"(src), "r"(sz));
}
__device__ __forceinline__ uint32_t smem_u32(const void* p) {
    return (uint32_t)__cvta_generic_to_shared(p);
}

// ---------------------------------------------------------------------------
__global__ void zero_cnt_kernel() {
    if (threadIdx.x < NEXP) g_cnt[threadIdx.x] = 0;
}

// warp-per-token router: 16 tokens per 512-thread block, Wr staged once/block
__global__ __launch_bounds__(512)
void router_kernel(const float* __restrict__ x, const float* __restrict__ wn,
                   const float* __restrict__ Wr, const float* __restrict__ br) {
    __shared__ float WrT[16][520];   // transposed [e][d], padded: ~33 KB

    const int tid = threadIdx.x, lane = tid & 31, w = tid >> 5;

    // stage Wr transposed: thread d scatters its 16 expert weights
    {
        const float4* wg = (const float4*)(Wr + tid * 16);
        float4 r0 = wg[0], r1 = wg[1], r2 = wg[2], r3 = wg[3];
        float v[16] = { r0.x,r0.y,r0.z,r0.w, r1.x,r1.y,r1.z,r1.w,
                        r2.x,r2.y,r2.z,r2.w, r3.x,r3.y,r3.z,r3.w };
        #pragma unroll
        for (int e = 0; e < 16; e++) WrT[e][tid] = v[e];
    }
    __syncthreads();

    const int n = blockIdx.x * 16 + w;

    float xl[16];
    #pragma unroll
    for (int i = 0; i < 16; i++) xl[i] = x[n*DIM + i*32 + lane];

    float ss = 0.f;
    #pragma unroll
    for (int i = 0; i < 16; i++) ss += xl[i] * xl[i];
    #pragma unroll
    for (int o = 16; o > 0; o >>= 1) ss += __shfl_down_sync(0xffffffffu, ss, o);
    ss = __shfl_sync(0xffffffffu, ss, 0);
    const float rinv = rsqrtf(ss / (float)DIM + 1e-10f);

    float xnl[16];
    #pragma unroll
    for (int i = 0; i < 16; i++) {
        xnl[i] = wn[i*32 + lane] * xl[i] * rinv;
        g_xn[n*DIM + i*32 + lane] = xnl[i];
    }

    float le[16];
    #pragma unroll
    for (int e = 0; e < 16; e++) {
        float p = 0.f;
        #pragma unroll
        for (int i = 0; i < 16; i++) p += xnl[i] * WrT[e][i*32 + lane];
        #pragma unroll
        for (int o = 16; o > 0; o >>= 1) p += __shfl_down_sync(0xffffffffu, p, o);
        le[e] = p;                       // complete on lane 0
    }

    if (lane == 0) {
        #pragma unroll
        for (int e = 0; e < 16; e++) le[e] += br[e];
        int i0 = 0; float b0 = le[0];
        #pragma unroll
        for (int e = 1; e < 16; e++) if (le[e] > b0) { b0 = le[e]; i0 = e; }
        int i1 = -1; float b1 = -1e30f;
        #pragma unroll
        for (int e = 0; e < 16; e++) {
            if (e == i0) continue;
            if (le[e] > b1) { b1 = le[e]; i1 = e; }
        }
        const float z  = expf(b1 - b0);
        const float w0 = 1.f / (1.f + z);
        const float w1 = z   / (1.f + z);
        const int p0 = atomicAdd(&g_cnt[i0], 1);
        const int p1 = atomicAdd(&g_cnt[i1], 1);
        g_tok[i0*NTOK + p0] = n;
        g_tok[i1*NTOK + p1] = n;
        g_gate[n*2+0] = w0;  g_gate[n*2+1] = w1;
        g_se[n*2+0]   = i0;  g_se[n*2+1]   = i1;
        g_sp[n*2+0]   = p0;  g_sp[n*2+1]   = p1;
    }
}

__global__ void offsets_kernel() {
    if (threadIdx.x == 0) {
        int s = 0;
        #pragma unroll
        for (int e = 0; e < NEXP; e++) { g_off[e] = s; s += g_cnt[e]; }
        g_off[NEXP] = s;
    }
}

// ---------------------------------------------------------------------------
// TF32 mma.sync GEMM, 3-stage cp.async pipeline, one barrier per k-tile.
// BM=128, BN=128, BK=16, 256 threads = 8 warps (4m x 2n), warp tile 32x64.
// Fragment-register batching: ALL 48 fragment LDS for the k-tile issue first,
// then all 32 HMMA fire back-to-back (acc-independent) — LDS latency is paid
// once per tile instead of per k8. Regs ~150 -> 1 CTA/SM (intentional).
// B staging: cp16 (R13-proven; R14's scalar-cp4 permuted layout regressed).
// FIRST=1: H[off+m] = silu(gather(xn)@W1[e] + b1[e])   (K=512,  LDB=HIDD)
// FIRST=0: Y[off+m] =        H        @W2[e] + b2[e]   (K=2048, LDB=DIM)
template<int FIRST>
__global__ __launch_bounds__(256)
void ffn_mma_kernel(const float* __restrict__ W, const float* __restrict__ bias) {
    const int e  = blockIdx.z;
    const int ne = g_cnt[e];
    const int m0 = blockIdx.x * 128;
    if (m0 >= ne) return;
    const int n0  = blockIdx.y * 128;
    const int off = g_off[e];
    const int tid  = threadIdx.x;
    const int lane = tid & 31, warp = tid >> 5;
    const int g = lane >> 2, t = lane & 3;
    const int wm = warp & 3, wn = warp >> 2;

    constexpr int K   = FIRST ? DIM  : HIDD;
    constexpr int LDB = FIRST ? HIDD : DIM;
    const float* Bp = W + (size_t)e * K * LDB + n0;

    // dynamic smem: 3 x As[128][20], then 3 x Bs[16][136]
    extern __shared__ __align__(16) float smem[];
    float (*As)[128][20] = (float (*)[128][20])smem;
    float (*Bs)[16][136] = (float (*)[16][136])(smem + 3*128*20);

    // A cp.async mapping: 2 float4/thread; idx = tid + p*256 -> row idx>>2, col (idx&3)*4
    const float* arp[2];
    int arow[2], acol[2];
    #pragma unroll
    for (int p = 0; p < 2; p++) {
        const int idx = tid + p*256;
        arow[p] = idx >> 2;
        acol[p] = (idx & 3) * 4;
        const int m = m0 + arow[p];
        const float* ap = nullptr;
        if (m < ne) {
            if (FIRST) ap = g_xn + (size_t)g_tok[e*NTOK + m] * DIM;
            else       ap = g_H  + (size_t)(off + m) * HIDD;
        }
        arp[p] = ap;
    }
    // B cp.async mapping: 2 float4/thread; idx -> row idx>>5, col (idx&31)*4
    int brow[2], bcol[2];
    #pragma unroll
    for (int p = 0; p < 2; p++) {
        const int idx = tid + p*256;
        brow[p] = idx >> 5;
        bcol[p] = (idx & 31) * 4;
    }

    float acc[2][8][4];
    #pragma unroll
    for (int mt = 0; mt < 2; mt++)
        #pragma unroll
        for (int nt = 0; nt < 8; nt++)
            #pragma unroll
            for (int i = 0; i < 4; i++) acc[mt][nt][i] = 0.f;

    auto issue = [&](int s, int k0) {
        #pragma unroll
        for (int p = 0; p < 2; p++) {
            const bool v = (arp[p] != nullptr);
            const float* src = v ? (arp[p] + k0 + acol[p]) : g_xn;  // dummy src when sz=0
            cp16(smem_u32(&As[s][arow[p]][acol[p]]), src, v);
        }
        #pragma unroll
        for (int p = 0; p < 2; p++) {
            cp16(smem_u32(&Bs[s][brow[p]][bcol[p]]),
                 Bp + (size_t)(k0 + brow[p]) * LDB + bcol[p], true);
        }
        asm volatile("cp.async.commit_group;");
    };

    constexpr int NT = K / 16;
    issue(0, 0);
    issue(1, 16);

    int cur = 0;                      // it % 3
    for (int it = 0; it < NT; it++) {
        if (it < NT - 1) asm volatile("cp.async.wait_group 1;");
        else             asm volatile("cp.async.wait_group 0;");
        __syncthreads();

        if (it + 2 < NT) {
            int s2 = cur + 2; if (s2 >= 3) s2 -= 3;
            issue(s2, (it + 2) * 16);
        }

        // ---- load ALL fragments for the k-tile (48 LDS), then 32 HMMA ----
        uint32_t af[2][2][4];
        uint32_t bf[2][8][2];
        #pragma unroll
        for (int kc = 0; kc < 2; kc++) {
            const int kk0 = kc * 8;
            #pragma unroll
            for (int mt = 0; mt < 2; mt++) {
                const int row = wm*32 + mt*16 + g;
                af[kc][mt][0] = __float_as_uint(As[cur][row  ][kk0 + t]);
                af[kc][mt][1] = __float_as_uint(As[cur][row+8][kk0 + t]);
                af[kc][mt][2] = __float_as_uint(As[cur][row  ][kk0 + t + 4]);
                af[kc][mt][3] = __float_as_uint(As[cur][row+8][kk0 + t + 4]);
            }
            #pragma unroll
            for (int nt = 0; nt < 8; nt++) {
                const int col = wn*64 + nt*8 + g;
                bf[kc][nt][0] = __float_as_uint(Bs[cur][kk0 + t    ][col]);
                bf[kc][nt][1] = __float_as_uint(Bs[cur][kk0 + t + 4][col]);
            }
        }
        #pragma unroll
        for (int kc = 0; kc < 2; kc++)
            #pragma unroll
            for (int mt = 0; mt < 2; mt++)
                #pragma unroll
                for (int nt = 0; nt < 8; nt++)
                    mma_tf32(acc[mt][nt], af[kc][mt], bf[kc][nt]);

        if (++cur == 3) cur = 0;
    }

    // ---- epilogue: bias (+silu), write ----
    const float* bpr = bias + (size_t)e * LDB + n0;
    #pragma unroll
    for (int mt = 0; mt < 2; mt++) {
        #pragma unroll
        for (int r = 0; r < 2; r++) {
            const int m = m0 + wm*32 + mt*16 + g + r*8;
            if (m >= ne) continue;
            float* orow = (FIRST ? g_H + (size_t)(off + m) * HIDD
                                 : g_Y + (size_t)(off + m) * DIM) + n0;
            #pragma unroll
            for (int nt = 0; nt < 8; nt++) {
                const int lc = wn*64 + nt*8 + 2*t;
                float v0 = acc[mt][nt][r*2+0] + bpr[lc];
                float v1 = acc[mt][nt][r*2+1] + bpr[lc+1];
                if (FIRST) {
                    v0 = v0 / (1.f + expf(-v0));   // silu
                    v1 = v1 / (1.f + expf(-v1));
                }
                *(float2*)(orow + lc) = make_float2(v0, v1);
            }
        }
    }
}

// out = x + g0*Y[row0] + g1*Y[row1]   (fixed k order -> deterministic)
__global__ void combine_kernel(const float* __restrict__ x, float* __restrict__ out) {
    const int idx = blockIdx.x * blockDim.x + threadIdx.x;
    if (idx >= NTOK*DIM) return;
    const int n = idx / DIM, d = idx % DIM;
    const int r0 = g_off[g_se[n*2+0]] + g_sp[n*2+0];
    const int r1 = g_off[g_se[n*2+1]] + g_sp[n*2+1];
    out[idx] = x[idx]
             + g_gate[n*2+0] * g_Y[(size_t)r0*DIM + d]
             + g_gate[n*2+1] * g_Y[(size_t)r1*DIM + d];
}

// ---------------------------------------------------------------------------
extern "C" void kernel_launch(void* const* d_in, const int* in_sizes, int n_in,
                              void* d_out, int out_size) {
    const float* x  = (const float*)d_in[0];
    const float* wn = (const float*)d_in[1];
    const float* Wr = (const float*)d_in[2];
    const float* br = (const float*)d_in[3];
    const float* W1 = (const float*)d_in[4];
    const float* b1 = (const float*)d_in[5];
    const float* W2 = (const float*)d_in[6];
    const float* b2 = (const float*)d_in[7];
    float* out = (float*)d_out;

    const int SMEM = (3*128*20 + 3*16*136) * 4;   // 56832 B
    cudaFuncSetAttribute(ffn_mma_kernel<1>,
                         cudaFuncAttributeMaxDynamicSharedMemorySize, SMEM);
    cudaFuncSetAttribute(ffn_mma_kernel<0>,
                         cudaFuncAttributeMaxDynamicSharedMemorySize, SMEM);

    zero_cnt_kernel<<<1, 32>>>();
    router_kernel<<<NTOK/16, 512>>>(x, wn, Wr, br);
    offsets_kernel<<<1, 32>>>();
    ffn_mma_kernel<1><<<dim3(16, HIDD/128, NEXP), 256, SMEM>>>(W1, b1);
    ffn_mma_kernel<0><<<dim3(16, DIM /128, NEXP), 256, SMEM>>>(W2, b2);
    combine_kernel<<<(NTOK*DIM + 255)/256, 256>>>(x, out);
}